// round 13
// baseline (speedup 1.0000x reference)
#include <cuda_runtime.h>
#include <math.h>

// 2-layer GATv2 (H=2 heads, C=32 ch) + edge MLP.
// N=50000 nodes, E=800000 edges (+N self loops). Output: E float logits.

#define HC 64
#define CC 32
#define MAXN 65536
#define MAXE 1048576
#define MAXEP (MAXE + MAXN)
#define SCANB 1024
#define MAXBLK 64

// ---- device scratch (static) ----
__device__ float  g_z[MAXN * HC];
__device__ float  g_hA[MAXN * HC];
__device__ float  g_hB[MAXN * HC];
__device__ int    g_deg[MAXN];
__device__ int    g_off[MAXN + 1];
__device__ int    g_cur[MAXN];
__device__ int    g_srcOf[MAXEP];
__device__ float2 g_eas[MAXEP];
__device__ float  g_u[MAXN * CC];
__device__ float  g_v[MAXN * CC];
__device__ float  g_easum[2];
__device__ float  g_gc[CC];
__device__ int    g_bsum[MAXBLK];
__device__ int    g_bbase[MAXBLK];

// ---- preprocessing ----
__global__ void k_zero(int N) {
    int i = blockIdx.x * blockDim.x + threadIdx.x;
    if (i < N) g_deg[i] = 0;
    if (i < 2) g_easum[i] = 0.f;
}

// fused: degree count (real edges) + edge_attr column sums
__global__ void k_deg_ea(const int* __restrict__ EI, const float* __restrict__ EA, int E) {
    __shared__ float s0[256], s1[256];
    int tid = threadIdx.x;
    float a0 = 0.f, a1 = 0.f;
    for (int e = blockIdx.x * 256 + tid; e < E; e += gridDim.x * 256) {
        atomicAdd(&g_deg[EI[E + e]], 1);
        float2 ea = ((const float2*)EA)[e];
        a0 += ea.x; a1 += ea.y;
    }
    s0[tid] = a0; s1[tid] = a1;
    __syncthreads();
    for (int s = 128; s; s >>= 1) {
        if (tid < s) { s0[tid] += s0[tid + s]; s1[tid] += s1[tid + s]; }
        __syncthreads();
    }
    if (tid == 0) {
        atomicAdd(&g_easum[0], s0[0]);
        atomicAdd(&g_easum[1], s1[0]);
    }
}

// scan stage 1: block-local exclusive scan (degree + 1 self loop per node)
__global__ void k_scan1(int N) {
    __shared__ int sh[SCANB];
    int tid = threadIdx.x;
    int i = blockIdx.x * SCANB + tid;
    int v = (i < N) ? g_deg[i] + 1 : 0;
    sh[tid] = v;
    __syncthreads();
    for (int s = 1; s < SCANB; s <<= 1) {
        int t = (tid >= s) ? sh[tid - s] : 0;
        __syncthreads();
        sh[tid] += t;
        __syncthreads();
    }
    if (i < N) g_off[i] = sh[tid] - v;
    if (tid == SCANB - 1) g_bsum[blockIdx.x] = sh[tid];
}

__global__ void k_scan2(int nb) {
    int tid = threadIdx.x;  // 64 threads
    int v = (tid < nb) ? g_bsum[tid] : 0;
    int x = v;
#pragma unroll
    for (int s = 1; s < 32; s <<= 1) {
        int t = __shfl_up_sync(0xffffffffu, x, s);
        if ((tid & 31) >= s) x += t;
    }
    __shared__ int w0;
    if (tid == 31) w0 = x;
    __syncthreads();
    if (tid >= 32) x += w0;
    if (tid < nb) g_bbase[tid] = x - v;
}

// scan stage 3: finalize offsets, init cur, place self-loop slot at end of segment
__global__ void k_scan3(int N, float invE) {
    int i = blockIdx.x * blockDim.x + threadIdx.x;
    if (i > N) return;
    int nb = (N + SCANB - 1) / SCANB;
    if (i == N) {
        g_off[N] = g_bbase[nb - 1] + g_bsum[nb - 1];
        return;
    }
    int o = g_off[i] + g_bbase[i / SCANB];
    g_off[i] = o;
    g_cur[i] = o;
    int slot = o + g_deg[i];             // last slot of segment = self loop
    g_srcOf[slot] = i;
    g_eas[slot] = make_float2(g_easum[0] * invE, g_easum[1] * invE);
}

__global__ void k_scatter(const int* __restrict__ EI, const float* __restrict__ EA, int E) {
    int e = blockIdx.x * blockDim.x + threadIdx.x;
    if (e >= E) return;
    int dst = EI[E + e];
    int pos = atomicAdd(&g_cur[dst], 1);
    g_srcOf[pos] = EI[e];
    g_eas[pos] = ((const float2*)EA)[e];
}

// ---- node linears ----
__global__ void k_lin0(const float* __restrict__ x, const float* __restrict__ W0,
                       const float* __restrict__ b0, int N) {
    int i = blockIdx.x * blockDim.x + threadIdx.x;
    if (i >= N * HC) return;
    int n = i >> 6, j = i & 63;
    g_z[i] = fmaf(x[2 * n], W0[j], fmaf(x[2 * n + 1], W0[64 + j], b0[j]));
}

__global__ void k_lin64(const float* __restrict__ W, const float* __restrict__ b, int N) {
    __shared__ float sh[8][64];
    int gw = (blockIdx.x * blockDim.x + threadIdx.x) >> 5;
    int lane = threadIdx.x & 31;
    int wl = threadIdx.x >> 5;
    if (gw >= N) return;
    sh[wl][lane]      = g_hA[gw * 64 + lane];
    sh[wl][32 + lane] = g_hA[gw * 64 + 32 + lane];
    __syncwarp();
    float a0 = b[lane], a1 = b[32 + lane];
#pragma unroll
    for (int k = 0; k < 64; k++) {
        float hk = sh[wl][k];
        a0 = fmaf(hk, W[k * 64 + lane], a0);
        a1 = fmaf(hk, W[k * 64 + 32 + lane], a1);
    }
    g_z[gw * 64 + lane]      = a0;
    g_z[gw * 64 + 32 + lane] = a1;
}

// ---- fused GATv2: logits + online softmax + aggregation + ELU ----
// warp per destination node. Lanes hold float2 channels:
// lanes 0-15 = head0 (ch 0-31), lanes 16-31 = head1 (ch 32-63).
// One z[src] gather per slot (online softmax rescaling). Unroll-2 (R4-proven).
__global__ void k_gatF(const float* __restrict__ We, const float* __restrict__ att,
                       const float* __restrict__ bias, int outSel, int N) {
    int d = (blockIdx.x * blockDim.x + threadIdx.x) >> 5;
    int lane = threadIdx.x & 31;
    if (d >= N) return;
    float* __restrict__ hout = outSel ? g_hB : g_hA;
    const float2* __restrict__ z2 = (const float2*)g_z;

    int off0 = g_off[d];
    int deg = g_off[d + 1] - off0;       // >= 1 (self loop)

    float2 zd   = z2[d * 32 + lane];
    float2 we0  = make_float2(We[lane * 2],      We[lane * 2 + 1]);       // row ea.x
    float2 we1  = make_float2(We[64 + lane * 2], We[64 + lane * 2 + 1]);  // row ea.y
    float2 at   = make_float2(att[lane * 2],     att[lane * 2 + 1]);

    float m = -1e30f, s = 0.f;
    float2 acc = make_float2(0.f, 0.f);

    int j = 0;
    for (; j + 2 <= deg; j += 2) {
        int b = off0 + j;
        int s1 = g_srcOf[b];
        int s2 = g_srcOf[b + 1];
        float2 e1 = g_eas[b];
        float2 e2 = g_eas[b + 1];
        float2 za = z2[s1 * 32 + lane];
        float2 zb = z2[s2 * 32 + lane];

        float t1x = zd.x + za.x + e1.x * we0.x + e1.y * we1.x;
        float t1y = zd.y + za.y + e1.x * we0.y + e1.y * we1.y;
        float t2x = zd.x + zb.x + e2.x * we0.x + e2.y * we1.x;
        float t2y = zd.y + zb.y + e2.x * we0.y + e2.y * we1.y;
        t1x = (t1x > 0.f) ? t1x : 0.2f * t1x;
        t1y = (t1y > 0.f) ? t1y : 0.2f * t1y;
        t2x = (t2x > 0.f) ? t2x : 0.2f * t2x;
        t2y = (t2y > 0.f) ? t2y : 0.2f * t2y;

        float a1 = t1x * at.x + t1y * at.y;
        float a2 = t2x * at.x + t2y * at.y;
        // reduce within 16-lane half (reduces head0 and head1 simultaneously)
#pragma unroll
        for (int o = 1; o < 16; o <<= 1) {
            a1 += __shfl_xor_sync(0xffffffffu, a1, o);
            a2 += __shfl_xor_sync(0xffffffffu, a2, o);
        }

        float M = fmaxf(m, fmaxf(a1, a2));
        float sc = __expf(m - M);
        float w1 = __expf(a1 - M);
        float w2 = __expf(a2 - M);
        s = s * sc + w1 + w2;
        acc.x = acc.x * sc + w1 * za.x + w2 * zb.x;
        acc.y = acc.y * sc + w1 * za.y + w2 * zb.y;
        m = M;
    }
    if (j < deg) {
        int b = off0 + j;
        int s1 = g_srcOf[b];
        float2 e1 = g_eas[b];
        float2 za = z2[s1 * 32 + lane];
        float t1x = zd.x + za.x + e1.x * we0.x + e1.y * we1.x;
        float t1y = zd.y + za.y + e1.x * we0.y + e1.y * we1.y;
        t1x = (t1x > 0.f) ? t1x : 0.2f * t1x;
        t1y = (t1y > 0.f) ? t1y : 0.2f * t1y;
        float a1 = t1x * at.x + t1y * at.y;
#pragma unroll
        for (int o = 1; o < 16; o <<= 1)
            a1 += __shfl_xor_sync(0xffffffffu, a1, o);
        float M = fmaxf(m, a1);
        float sc = __expf(m - M);
        float w1 = __expf(a1 - M);
        s = s * sc + w1;
        acc.x = acc.x * sc + w1 * za.x;
        acc.y = acc.y * sc + w1 * za.y;
    }

    float inv = 1.f / (s + 1e-16f);
    float2 bias2 = ((const float2*)bias)[lane];
    float o0 = acc.x * inv + bias2.x;
    float o1 = acc.y * inv + bias2.y;
    o0 = (o0 > 0.f) ? o0 : (__expf(o0) - 1.f);
    o1 = (o1 > 0.f) ? o1 : (__expf(o1) - 1.f);
    ((float2*)hout)[d * 32 + lane] = make_float2(o0, o1);
}

// ---- final edge MLP (factored); goal vector fused into the spare warp gw==N ----
__global__ void k_uv(const float* __restrict__ Wm1, const float* __restrict__ bm1,
                     const int* __restrict__ dest, int N) {
    __shared__ float sh[8][64];
    int gw = (blockIdx.x * blockDim.x + threadIdx.x) >> 5;
    int lane = threadIdx.x & 31;
    int wl = threadIdx.x >> 5;
    if (gw >= N) {
        if (gw == N) {
            // goal channel precompute: gc = bm1 + hB[dest] @ Wm1[128:192]
            int d = dest[0];
            float acc = bm1[lane];
            for (int k = 0; k < 64; k++)
                acc = fmaf(g_hB[d * 64 + k], Wm1[(128 + k) * 32 + lane], acc);
            g_gc[lane] = acc;
        }
        return;
    }
    sh[wl][lane]      = g_hB[gw * 64 + lane];
    sh[wl][32 + lane] = g_hB[gw * 64 + 32 + lane];
    __syncwarp();
    float au = 0.f, av = 0.f;
#pragma unroll
    for (int k = 0; k < 64; k++) {
        float hk = sh[wl][k];
        au = fmaf(hk, Wm1[k * 32 + lane], au);
        av = fmaf(hk, Wm1[(64 + k) * 32 + lane], av);
    }
    g_u[gw * 32 + lane] = au;
    g_v[gw * 32 + lane] = av;
}

// 2 edges per warp, float2 channel lanes
__global__ void k_edge(const int* __restrict__ EI, const float* __restrict__ EA,
                       const float* __restrict__ Wm1, const float* __restrict__ Wm2,
                       const float* __restrict__ bm2, float* __restrict__ out, int E) {
    int warpId = (blockIdx.x * blockDim.x + threadIdx.x) >> 5;
    int lane = threadIdx.x & 31;
    int sub = lane & 15;
    if (warpId * 2 >= E) return;
    int e = warpId * 2 + (lane >> 4);
    bool valid = (e < E);
    if (!valid) e = E - 1;

    int src = EI[e], dst = EI[E + e];
    float2 ea = ((const float2*)EA)[e];
    float2 u2 = ((const float2*)g_u)[src * 16 + sub];
    float2 v2 = ((const float2*)g_v)[dst * 16 + sub];
    float2 gc2 = ((const float2*)g_gc)[sub];
    float2 wa  = ((const float2*)(Wm1 + 192 * 32))[sub];
    float2 wb  = ((const float2*)(Wm1 + 193 * 32))[sub];
    float2 wm2 = ((const float2*)Wm2)[sub];

    float t0 = u2.x + v2.x + gc2.x + ea.x * wa.x + ea.y * wb.x;
    float t1 = u2.y + v2.y + gc2.y + ea.x * wa.y + ea.y * wb.y;
    t0 = fmaxf(t0, 0.f);
    t1 = fmaxf(t1, 0.f);
    float p = t0 * wm2.x + t1 * wm2.y;
    p += __shfl_xor_sync(0xffffffffu, p, 1);
    p += __shfl_xor_sync(0xffffffffu, p, 2);
    p += __shfl_xor_sync(0xffffffffu, p, 4);
    p += __shfl_xor_sync(0xffffffffu, p, 8);
    if (sub == 0 && valid) out[e] = p + __ldg(bm2);
}

extern "C" void kernel_launch(void* const* d_in, const int* in_sizes, int n_in,
                              void* d_out, int out_size) {
    const float* x     = (const float*)d_in[0];
    const int*   EI    = (const int*)  d_in[1];
    const float* EA    = (const float*)d_in[2];
    const int*   dest  = (const int*)  d_in[3];
    const float* W0    = (const float*)d_in[4];
    const float* b0    = (const float*)d_in[5];
    const float* We0   = (const float*)d_in[6];
    const float* att0  = (const float*)d_in[7];
    const float* bias0 = (const float*)d_in[8];
    const float* W1    = (const float*)d_in[9];
    const float* b1    = (const float*)d_in[10];
    const float* We1   = (const float*)d_in[11];
    const float* att1  = (const float*)d_in[12];
    const float* bias1 = (const float*)d_in[13];
    const float* Wm1   = (const float*)d_in[14];
    const float* bm1   = (const float*)d_in[15];
    const float* Wm2   = (const float*)d_in[16];
    const float* bm2   = (const float*)d_in[17];

    int N  = in_sizes[0] / 2;
    int E  = in_sizes[1] / 2;
    int nb = (N + SCANB - 1) / SCANB;
    float invE = 1.0f / (float)E;
    float* out = (float*)d_out;

    // CSR build
    k_zero   <<<(N + 255) / 256, 256>>>(N);
    k_deg_ea <<<512, 256>>>(EI, EA, E);
    k_scan1  <<<nb, SCANB>>>(N);
    k_scan2  <<<1, 64>>>(nb);
    k_scan3  <<<(N + 256) / 256, 256>>>(N, invE);
    k_scatter<<<(E + 255) / 256, 256>>>(EI, EA, E);

    int nodeBlocks = (N + 7) / 8;
    int uvBlocks   = (N + 8) / 8;        // one spare warp (gw == N) for goal vector

    // layer 0
    k_lin0 <<<(N * 64 + 255) / 256, 256>>>(x, W0, b0, N);
    k_gatF <<<nodeBlocks, 256>>>(We0, att0, bias0, /*outSel=*/0, N);

    // layer 1
    k_lin64<<<nodeBlocks, 256>>>(W1, b1, N);
    k_gatF <<<nodeBlocks, 256>>>(We1, att1, bias1, /*outSel=*/1, N);

    // edge MLP (goal fused into k_uv's spare warp)
    k_uv   <<<uvBlocks, 256>>>(Wm1, bm1, dest, N);
    k_edge <<<(E + 15) / 16, 256>>>(EI, EA, Wm1, Wm2, bm2, out, E);
}

// round 15
// speedup vs baseline: 1.5810x; 1.5810x over previous
#include <cuda_runtime.h>
#include <math.h>

// 2-layer GATv2 (H=2 heads, C=32 ch) + edge MLP.
// N=50000 nodes, E=800000 edges (+N self loops). Output: E float logits.

#define HC 64
#define CC 32
#define MAXN 65536
#define MAXE 1048576
#define MAXEP (MAXE + MAXN)
#define SCANB 1024
#define MAXBLK 64

// ---- device scratch (static) ----
__device__ float  g_z[MAXN * HC];
__device__ float  g_hA[MAXN * HC];
__device__ float  g_hB[MAXN * HC];
__device__ int    g_deg[MAXN];
__device__ int    g_off[MAXN + 1];
__device__ int    g_cur[MAXN];
__device__ int    g_srcOf[MAXEP];
__device__ float2 g_eas[MAXEP];
__device__ float  g_u[MAXN * CC];
__device__ float  g_v[MAXN * CC];
__device__ float  g_easum[2];
__device__ float  g_gc[CC];
__device__ int    g_bsum[MAXBLK];
__device__ int    g_bbase[MAXBLK];

// ---- preprocessing ----
__global__ void k_zero(int N) {
    int i = blockIdx.x * blockDim.x + threadIdx.x;
    if (i < N) g_deg[i] = 0;
    if (i < 2) g_easum[i] = 0.f;
}

__global__ void k_deg_ea(const int* __restrict__ EI, const float* __restrict__ EA, int E) {
    __shared__ float s0[256], s1[256];
    int tid = threadIdx.x;
    float a0 = 0.f, a1 = 0.f;
    for (int e = blockIdx.x * 256 + tid; e < E; e += gridDim.x * 256) {
        atomicAdd(&g_deg[EI[E + e]], 1);
        float2 ea = ((const float2*)EA)[e];
        a0 += ea.x; a1 += ea.y;
    }
    s0[tid] = a0; s1[tid] = a1;
    __syncthreads();
    for (int s = 128; s; s >>= 1) {
        if (tid < s) { s0[tid] += s0[tid + s]; s1[tid] += s1[tid + s]; }
        __syncthreads();
    }
    if (tid == 0) {
        atomicAdd(&g_easum[0], s0[0]);
        atomicAdd(&g_easum[1], s1[0]);
    }
}

__global__ void k_scan1(int N) {
    __shared__ int sh[SCANB];
    int tid = threadIdx.x;
    int i = blockIdx.x * SCANB + tid;
    int v = (i < N) ? g_deg[i] + 1 : 0;
    sh[tid] = v;
    __syncthreads();
    for (int s = 1; s < SCANB; s <<= 1) {
        int t = (tid >= s) ? sh[tid - s] : 0;
        __syncthreads();
        sh[tid] += t;
        __syncthreads();
    }
    if (i < N) g_off[i] = sh[tid] - v;
    if (tid == SCANB - 1) g_bsum[blockIdx.x] = sh[tid];
}

__global__ void k_scan2(int nb) {
    int tid = threadIdx.x;  // 64 threads
    int v = (tid < nb) ? g_bsum[tid] : 0;
    int x = v;
#pragma unroll
    for (int s = 1; s < 32; s <<= 1) {
        int t = __shfl_up_sync(0xffffffffu, x, s);
        if ((tid & 31) >= s) x += t;
    }
    __shared__ int w0;
    if (tid == 31) w0 = x;
    __syncthreads();
    if (tid >= 32) x += w0;
    if (tid < nb) g_bbase[tid] = x - v;
}

__global__ void k_scan3(int N, float invE) {
    int i = blockIdx.x * blockDim.x + threadIdx.x;
    if (i > N) return;
    int nb = (N + SCANB - 1) / SCANB;
    if (i == N) {
        g_off[N] = g_bbase[nb - 1] + g_bsum[nb - 1];
        return;
    }
    int o = g_off[i] + g_bbase[i / SCANB];
    g_off[i] = o;
    g_cur[i] = o;
    int slot = o + g_deg[i];             // last slot of segment = self loop
    g_srcOf[slot] = i;
    g_eas[slot] = make_float2(g_easum[0] * invE, g_easum[1] * invE);
}

__global__ void k_scatter(const int* __restrict__ EI, const float* __restrict__ EA, int E) {
    int e = blockIdx.x * blockDim.x + threadIdx.x;
    if (e >= E) return;
    int dst = EI[E + e];
    int pos = atomicAdd(&g_cur[dst], 1);
    g_srcOf[pos] = EI[e];
    g_eas[pos] = ((const float2*)EA)[e];
}

// ---- node linears ----
__global__ void k_lin0(const float* __restrict__ x, const float* __restrict__ W0,
                       const float* __restrict__ b0, int N) {
    int i = blockIdx.x * blockDim.x + threadIdx.x;
    if (i >= N * HC) return;
    int n = i >> 6, j = i & 63;
    g_z[i] = fmaf(x[2 * n], W0[j], fmaf(x[2 * n + 1], W0[64 + j], b0[j]));
}

__global__ void k_lin64(const float* __restrict__ W, const float* __restrict__ b, int N) {
    __shared__ float sh[8][64];
    int gw = (blockIdx.x * blockDim.x + threadIdx.x) >> 5;
    int lane = threadIdx.x & 31;
    int wl = threadIdx.x >> 5;
    if (gw >= N) return;
    sh[wl][lane]      = g_hA[gw * 64 + lane];
    sh[wl][32 + lane] = g_hA[gw * 64 + 32 + lane];
    __syncwarp();
    float a0 = b[lane], a1 = b[32 + lane];
#pragma unroll
    for (int k = 0; k < 64; k++) {
        float hk = sh[wl][k];
        a0 = fmaf(hk, W[k * 64 + lane], a0);
        a1 = fmaf(hk, W[k * 64 + 32 + lane], a1);
    }
    g_z[gw * 64 + lane]      = a0;
    g_z[gw * 64 + 32 + lane] = a1;
}

// ---- fused GATv2: logits + online softmax + aggregation + ELU ----
// Warp per node. Each 16-lane HALF processes its own slot stream (float4 = 4 ch/lane).
// Within a half: lanes 0-7 hold head0 channels, 8-15 head1 -> per-head logit
// reduction over aligned 8-lane groups (3 SHFLs, all 4 groups simultaneously).
// Each lane's (m,s) online state is per-ITS-head. Halves flash-merged at the end.
__global__ void __launch_bounds__(256) k_gatF(
        const float* __restrict__ We, const float* __restrict__ att,
        const float* __restrict__ bias, int outSel, int N) {
    int d = (blockIdx.x * blockDim.x + threadIdx.x) >> 5;
    int lane = threadIdx.x & 31;
    int half = lane >> 4;
    int sub  = lane & 15;                // 4 channels: sub*4 .. sub*4+3
    if (d >= N) return;
    float* __restrict__ hout = outSel ? g_hB : g_hA;
    const float4* __restrict__ z4 = (const float4*)g_z;

    int off0 = g_off[d];
    int deg  = g_off[d + 1] - off0;      // >= 1 (self loop)

    float4 zd  = z4[d * 16 + sub];
    float4 we0 = ((const float4*)We)[sub];        // We row 0 (ea.x)
    float4 we1 = ((const float4*)We)[16 + sub];   // We row 1 (ea.y)
    float4 at4 = ((const float4*)att)[sub];

    float m = -1e30f, s = 0.f;
    float4 acc = make_float4(0.f, 0.f, 0.f, 0.f);

    int j = 0;
    // main loop: 4 slots per warp iteration (2 per half)
    for (; j + 4 <= deg; j += 4) {
        int b = off0 + j + half * 2;
        int sA = g_srcOf[b];
        int sB = g_srcOf[b + 1];
        float2 eA = g_eas[b];
        float2 eB = g_eas[b + 1];
        float4 zA = z4[sA * 16 + sub];
        float4 zB = z4[sB * 16 + sub];

        float4 tA, tB;
        tA.x = zd.x + zA.x + eA.x * we0.x + eA.y * we1.x;
        tA.y = zd.y + zA.y + eA.x * we0.y + eA.y * we1.y;
        tA.z = zd.z + zA.z + eA.x * we0.z + eA.y * we1.z;
        tA.w = zd.w + zA.w + eA.x * we0.w + eA.y * we1.w;
        tB.x = zd.x + zB.x + eB.x * we0.x + eB.y * we1.x;
        tB.y = zd.y + zB.y + eB.x * we0.y + eB.y * we1.y;
        tB.z = zd.z + zB.z + eB.x * we0.z + eB.y * we1.z;
        tB.w = zd.w + zB.w + eB.x * we0.w + eB.y * we1.w;
        tA.x = (tA.x > 0.f) ? tA.x : 0.2f * tA.x;
        tA.y = (tA.y > 0.f) ? tA.y : 0.2f * tA.y;
        tA.z = (tA.z > 0.f) ? tA.z : 0.2f * tA.z;
        tA.w = (tA.w > 0.f) ? tA.w : 0.2f * tA.w;
        tB.x = (tB.x > 0.f) ? tB.x : 0.2f * tB.x;
        tB.y = (tB.y > 0.f) ? tB.y : 0.2f * tB.y;
        tB.z = (tB.z > 0.f) ? tB.z : 0.2f * tB.z;
        tB.w = (tB.w > 0.f) ? tB.w : 0.2f * tB.w;

        float aA = tA.x * at4.x + tA.y * at4.y + tA.z * at4.z + tA.w * at4.w;
        float aB = tB.x * at4.x + tB.y * at4.y + tB.z * at4.z + tB.w * at4.w;
        // per-head reduction over aligned 8-lane groups
#pragma unroll
        for (int o = 1; o < 8; o <<= 1) {
            aA += __shfl_xor_sync(0xffffffffu, aA, o);
            aB += __shfl_xor_sync(0xffffffffu, aB, o);
        }

        float M = fmaxf(m, fmaxf(aA, aB));
        float sc = __expf(m - M);
        float wA = __expf(aA - M);
        float wB = __expf(aB - M);
        s = s * sc + wA + wB;
        acc.x = acc.x * sc + wA * zA.x + wB * zB.x;
        acc.y = acc.y * sc + wA * zA.y + wB * zB.y;
        acc.z = acc.z * sc + wA * zA.z + wB * zB.z;
        acc.w = acc.w * sc + wA * zA.w + wB * zB.w;
        m = M;
    }
    // tail: 2 slots per step (one per half), predicated with -inf logit
    for (; j < deg; j += 2) {
        int jj = j + half;
        bool valid = (jj < deg);
        int b = off0 + (valid ? jj : 0);
        int sA = g_srcOf[b];
        float2 eA = g_eas[b];
        float4 zA = z4[sA * 16 + sub];
        float4 tA;
        tA.x = zd.x + zA.x + eA.x * we0.x + eA.y * we1.x;
        tA.y = zd.y + zA.y + eA.x * we0.y + eA.y * we1.y;
        tA.z = zd.z + zA.z + eA.x * we0.z + eA.y * we1.z;
        tA.w = zd.w + zA.w + eA.x * we0.w + eA.y * we1.w;
        tA.x = (tA.x > 0.f) ? tA.x : 0.2f * tA.x;
        tA.y = (tA.y > 0.f) ? tA.y : 0.2f * tA.y;
        tA.z = (tA.z > 0.f) ? tA.z : 0.2f * tA.z;
        tA.w = (tA.w > 0.f) ? tA.w : 0.2f * tA.w;
        float aA = tA.x * at4.x + tA.y * at4.y + tA.z * at4.z + tA.w * at4.w;
#pragma unroll
        for (int o = 1; o < 8; o <<= 1)
            aA += __shfl_xor_sync(0xffffffffu, aA, o);
        if (!valid) aA = -INFINITY;      // exp -> 0, contributes nothing
        float M = fmaxf(m, aA);
        float sc = __expf(m - M);
        float wA = __expf(aA - M);
        s = s * sc + wA;
        acc.x = acc.x * sc + wA * zA.x;
        acc.y = acc.y * sc + wA * zA.y;
        acc.z = acc.z * sc + wA * zA.z;
        acc.w = acc.w * sc + wA * zA.w;
        m = M;
    }

    // merge the two halves' online states (partner = lane ^ 16, same channels/head)
    float mo = __shfl_xor_sync(0xffffffffu, m, 16);
    float so = __shfl_xor_sync(0xffffffffu, s, 16);
    float4 ao;
    ao.x = __shfl_xor_sync(0xffffffffu, acc.x, 16);
    ao.y = __shfl_xor_sync(0xffffffffu, acc.y, 16);
    ao.z = __shfl_xor_sync(0xffffffffu, acc.z, 16);
    ao.w = __shfl_xor_sync(0xffffffffu, acc.w, 16);
    float M = fmaxf(m, mo);
    float c0 = __expf(m - M);
    float c1 = __expf(mo - M);
    s = s * c0 + so * c1;
    acc.x = acc.x * c0 + ao.x * c1;
    acc.y = acc.y * c0 + ao.y * c1;
    acc.z = acc.z * c0 + ao.z * c1;
    acc.w = acc.w * c0 + ao.w * c1;

    float inv = 1.f / (s + 1e-16f);
    float4 b4 = ((const float4*)bias)[sub];
    float4 o4;
    o4.x = acc.x * inv + b4.x;
    o4.y = acc.y * inv + b4.y;
    o4.z = acc.z * inv + b4.z;
    o4.w = acc.w * inv + b4.w;
    o4.x = (o4.x > 0.f) ? o4.x : (__expf(o4.x) - 1.f);
    o4.y = (o4.y > 0.f) ? o4.y : (__expf(o4.y) - 1.f);
    o4.z = (o4.z > 0.f) ? o4.z : (__expf(o4.z) - 1.f);
    o4.w = (o4.w > 0.f) ? o4.w : (__expf(o4.w) - 1.f);
    if (half == 0) ((float4*)hout)[d * 16 + sub] = o4;
}

// ---- final edge MLP (factored); goal vector fused into the spare warp gw==N ----
__global__ void k_uv(const float* __restrict__ Wm1, const float* __restrict__ bm1,
                     const int* __restrict__ dest, int N) {
    __shared__ float sh[8][64];
    int gw = (blockIdx.x * blockDim.x + threadIdx.x) >> 5;
    int lane = threadIdx.x & 31;
    int wl = threadIdx.x >> 5;
    if (gw >= N) {
        if (gw == N) {
            int d = dest[0];
            float acc = bm1[lane];
            for (int k = 0; k < 64; k++)
                acc = fmaf(g_hB[d * 64 + k], Wm1[(128 + k) * 32 + lane], acc);
            g_gc[lane] = acc;
        }
        return;
    }
    sh[wl][lane]      = g_hB[gw * 64 + lane];
    sh[wl][32 + lane] = g_hB[gw * 64 + 32 + lane];
    __syncwarp();
    float au = 0.f, av = 0.f;
#pragma unroll
    for (int k = 0; k < 64; k++) {
        float hk = sh[wl][k];
        au = fmaf(hk, Wm1[k * 32 + lane], au);
        av = fmaf(hk, Wm1[(64 + k) * 32 + lane], av);
    }
    g_u[gw * 32 + lane] = au;
    g_v[gw * 32 + lane] = av;
}

// 2 edges per warp, float2 channel lanes
__global__ void k_edge(const int* __restrict__ EI, const float* __restrict__ EA,
                       const float* __restrict__ Wm1, const float* __restrict__ Wm2,
                       const float* __restrict__ bm2, float* __restrict__ out, int E) {
    int warpId = (blockIdx.x * blockDim.x + threadIdx.x) >> 5;
    int lane = threadIdx.x & 31;
    int sub = lane & 15;
    if (warpId * 2 >= E) return;
    int e = warpId * 2 + (lane >> 4);
    bool valid = (e < E);
    if (!valid) e = E - 1;

    int src = EI[e], dst = EI[E + e];
    float2 ea = ((const float2*)EA)[e];
    float2 u2 = ((const float2*)g_u)[src * 16 + sub];
    float2 v2 = ((const float2*)g_v)[dst * 16 + sub];
    float2 gc2 = ((const float2*)g_gc)[sub];
    float2 wa  = ((const float2*)(Wm1 + 192 * 32))[sub];
    float2 wb  = ((const float2*)(Wm1 + 193 * 32))[sub];
    float2 wm2 = ((const float2*)Wm2)[sub];

    float t0 = u2.x + v2.x + gc2.x + ea.x * wa.x + ea.y * wb.x;
    float t1 = u2.y + v2.y + gc2.y + ea.x * wa.y + ea.y * wb.y;
    t0 = fmaxf(t0, 0.f);
    t1 = fmaxf(t1, 0.f);
    float p = t0 * wm2.x + t1 * wm2.y;
    p += __shfl_xor_sync(0xffffffffu, p, 1);
    p += __shfl_xor_sync(0xffffffffu, p, 2);
    p += __shfl_xor_sync(0xffffffffu, p, 4);
    p += __shfl_xor_sync(0xffffffffu, p, 8);
    if (sub == 0 && valid) out[e] = p + __ldg(bm2);
}

extern "C" void kernel_launch(void* const* d_in, const int* in_sizes, int n_in,
                              void* d_out, int out_size) {
    const float* x     = (const float*)d_in[0];
    const int*   EI    = (const int*)  d_in[1];
    const float* EA    = (const float*)d_in[2];
    const int*   dest  = (const int*)  d_in[3];
    const float* W0    = (const float*)d_in[4];
    const float* b0    = (const float*)d_in[5];
    const float* We0   = (const float*)d_in[6];
    const float* att0  = (const float*)d_in[7];
    const float* bias0 = (const float*)d_in[8];
    const float* W1    = (const float*)d_in[9];
    const float* b1    = (const float*)d_in[10];
    const float* We1   = (const float*)d_in[11];
    const float* att1  = (const float*)d_in[12];
    const float* bias1 = (const float*)d_in[13];
    const float* Wm1   = (const float*)d_in[14];
    const float* bm1   = (const float*)d_in[15];
    const float* Wm2   = (const float*)d_in[16];
    const float* bm2   = (const float*)d_in[17];

    int N  = in_sizes[0] / 2;
    int E  = in_sizes[1] / 2;
    int nb = (N + SCANB - 1) / SCANB;
    float invE = 1.0f / (float)E;
    float* out = (float*)d_out;

    // CSR build
    k_zero   <<<(N + 255) / 256, 256>>>(N);
    k_deg_ea <<<512, 256>>>(EI, EA, E);
    k_scan1  <<<nb, SCANB>>>(N);
    k_scan2  <<<1, 64>>>(nb);
    k_scan3  <<<(N + 256) / 256, 256>>>(N, invE);
    k_scatter<<<(E + 255) / 256, 256>>>(EI, EA, E);

    int nodeBlocks = (N + 7) / 8;
    int uvBlocks   = (N + 8) / 8;        // one spare warp (gw == N) for goal vector

    // layer 0
    k_lin0 <<<(N * 64 + 255) / 256, 256>>>(x, W0, b0, N);
    k_gatF <<<nodeBlocks, 256>>>(We0, att0, bias0, /*outSel=*/0, N);

    // layer 1
    k_lin64<<<nodeBlocks, 256>>>(W1, b1, N);
    k_gatF <<<nodeBlocks, 256>>>(We1, att1, bias1, /*outSel=*/1, N);

    // edge MLP (goal fused into k_uv's spare warp)
    k_uv   <<<uvBlocks, 256>>>(Wm1, bm1, dest, N);
    k_edge <<<(E + 15) / 16, 256>>>(EI, EA, Wm1, Wm2, bm2, out, E);
}